// round 16
// baseline (speedup 1.0000x reference)
#include <cuda_runtime.h>
#include <math.h>
#include <stdint.h>

#define INSZ   1024
#define HID    2048
#define OUTSZ  1024
#define MSTEPS 100
#define NSTEPS 101
#define EPSH   0.01f

#define NBLK   128
#define NTHR   1024
#define NWARP  32
#define UPB    16            // hidden units per block (2 warps per unit)

// ---- persistent scratch (device globals; no allocations allowed) ----
__device__ float g_H[NSTEPS][HID];
__device__ float g_C[NSTEPS][HID];
__device__ float g_partial[NSTEPS][NBLK];   // per-block halt-dot partials (overwritten, no init)
__device__ unsigned int g_count = 0;
__device__ unsigned int g_gen   = 0;

// Generation-counter grid barrier (persists across graph replays). PROVEN (R7..R13).
__device__ __forceinline__ void grid_sync(unsigned int &target) {
    __syncthreads();
    if (threadIdx.x == 0) {
        __threadfence();
        unsigned int a = atomicAdd(&g_count, 1u);
        if (a == NBLK - 1) {
            g_count = 0u;
            __threadfence();
            atomicAdd(&g_gen, 1u);
        } else {
            while (atomicAdd(&g_gen, 0u) < target) __nanosleep(40);
        }
        __threadfence();
        target++;
    }
    __syncthreads();
}

__device__ __forceinline__ float warp_sum(float v) {
    #pragma unroll
    for (int o = 16; o > 0; o >>= 1) v += __shfl_xor_sync(0xffffffffu, v, o);
    return v;
}

__device__ __forceinline__ float sigm(float v) { return 1.0f / (1.0f + expf(-v)); }

// ---- cp.async staging of one 512-float chunk into a 2KB buffer ----
__device__ __forceinline__ void stage16(uint32_t sbuf, const float* g, int lane) {
    #pragma unroll
    for (int o = 0; o < 4; o++)
        asm volatile("cp.async.cg.shared.global [%0], [%1], 16;"
                     :: "r"(sbuf + (uint32_t)((o*32 + lane)*16)),
                        "l"(g + (o*32 + lane)*4) : "memory");
    asm volatile("cp.async.commit_group;" ::: "memory");
}
#define CP_WAIT(N) asm volatile("cp.async.wait_group %0;" :: "n"(N) : "memory")

// 512-float chunk dot: weights from smem, operand from registers
__device__ __forceinline__ float dotR(const float4* w, const float4 h[4], int lane) {
    float acc = 0.0f;
    #pragma unroll
    for (int k = 0; k < 4; k++) {
        const float4 wv = w[k*32 + lane];
        acc += wv.x*h[k].x + wv.y*h[k].y + wv.z*h[k].z + wv.w*h[k].w;
    }
    return acc;
}

__device__ __forceinline__ float4 ldcg4(const float4* p) {
    float4 v;
    asm volatile("ld.global.cg.v4.f32 {%0,%1,%2,%3}, [%4];"
                 : "=f"(v.x), "=f"(v.y), "=f"(v.z), "=f"(v.w) : "l"(p));
    return v;
}

__global__ __launch_bounds__(NTHR, 1) void act_lstm(
    const float* __restrict__ x,      const float* __restrict__ h0,
    const float* __restrict__ c0,     const float* __restrict__ W_ih,
    const float* __restrict__ b_ih,   const float* __restrict__ W_hh,
    const float* __restrict__ b_hh,   const float* __restrict__ w_halt,
    const float* __restrict__ b_halt, const float* __restrict__ W_out,
    const float* __restrict__ b_out,  float* __restrict__ out)
{
    const int tid  = threadIdx.x;
    const int warp = tid >> 5;
    const int lane = tid & 31;
    const int u    = warp >> 1;          // unit slot within block (0..15)
    const int half = warp & 1;           // K-half owned by this warp
    const int j    = blockIdx.x * UPB + u;

    extern __shared__ float dsm[];
    float* s_h = dsm;                    // 2048 floats (epilogue weighted-h only)
    float* wb  = dsm + 2048 + warp*1536; // per-warp 3 x 512-float buffers
    const float4* fb[3] = { (const float4*)wb, (const float4*)(wb + 512), (const float4*)(wb + 1024) };
    uint32_t bb0 = (uint32_t)__cvta_generic_to_shared(wb);
    uint32_t bb[3] = { bb0, bb0 + 2048u, bb0 + 4096u };

    __shared__ float s_acc[UPB][2][4];
    __shared__ float s_p[NSTEPS];
    __shared__ float s_part[UPB];
    __shared__ float s_bcast[4];         // [0]=r [1]=sum_w [2]=n [3]=halt flag
    __shared__ float s_wo[8][4];

    unsigned int gen_target = 0;
    if (tid == 0) gen_target = g_gen + 1u;

    // warp's 4 gate rows; each warp owns 1024 K-columns (2 chunks of 512)
    const float* ihs[4];
    const float* whs[4];
    #pragma unroll
    for (int g = 0; g < 4; g++) {
        const int row = j + g * HID;
        ihs[g] = W_ih + (size_t)row * (INSZ + 1) + 1 + half * (INSZ / 2);
        whs[g] = W_hh + (size_t)row * HID        +     half * (HID / 2);
    }

    // ---- commit first 3 W_hh groups IMMEDIATELY (entry condition of the ladder) ----
    stage16(bb[0], whs[0], lane);   // G0c0 -> B0
    stage16(bb[1], whs[1], lane);   // G1c0 -> B1
    stage16(bb[2], whs[2], lane);   // G2c0 -> B2

    // L2-prefetch this block's W_out rows for the epilogue (fire and forget)
    if (tid < 512) {
        const float* wop = W_out + (size_t)(blockIdx.x * 8) * HID + tid * 32;
        asm volatile("prefetch.global.L2 [%0];" :: "l"(wop));
    }

    // scalars on lane0/half0
    float b_sum[4] = {0,0,0,0}, wfl[4] = {0,0,0,0};
    float whj = 0.0f, cprev = 0.0f, bh = 0.0f, csum = 0.0f;
    if (half == 0 && lane == 0) {
        #pragma unroll
        for (int g = 0; g < 4; g++) {
            const int row = j + g * HID;
            b_sum[g] = b_ih[row] + b_hh[row];
            wfl[g]   = W_ih[(size_t)row * (INSZ + 1)];
        }
        whj   = w_halt[j];
        cprev = c0[j];
    }
    if (tid == 0) bh = b_halt[0];

    // ---- x-dot via independent scalar LDGs (overlaps the in-flight W_hh groups) ----
    float accih[4];
    {
        float xs[16];
        #pragma unroll
        for (int k = 0; k < 16; k++) xs[k] = __ldg(x + half*512 + k*32 + lane);
        #pragma unroll
        for (int g = 0; g < 4; g++) {
            const float* wp = ihs[g];
            float acc = 0.0f;
            #pragma unroll
            for (int k = 0; k < 16; k++) acc += __ldg(wp + k*32 + lane) * xs[k];
            accih[g] = acc;
        }
    }

    // ======== step 0: canonical 8-chunk ladder against h0 ========
    float4 hr[4];
    float a0, a1, a2, a3;
    const float4* hp4 = (const float4*)h0;
    #pragma unroll
    for (int k = 0; k < 4; k++) hr[k] = ldcg4(hp4 + half*256 + k*32 + lane);          // c0

    CP_WAIT(2); a0 = accih[0] + dotR(fb[0], hr, lane);
    CP_WAIT(1); a1 = accih[1] + dotR(fb[1], hr, lane);  stage16(bb[0], whs[3],       lane); // G3c0 -> B0
    CP_WAIT(1); a2 = accih[2] + dotR(fb[2], hr, lane);  stage16(bb[1], whs[0] + 512, lane); // G0c1 -> B1
    CP_WAIT(1); a3 = accih[3] + dotR(fb[0], hr, lane);  stage16(bb[2], whs[1] + 512, lane); // G1c1 -> B2
    #pragma unroll
    for (int k = 0; k < 4; k++) hr[k] = ldcg4(hp4 + half*256 + 128 + k*32 + lane);    // c1
    CP_WAIT(1); a0 += dotR(fb[1], hr, lane);  stage16(bb[0], whs[2] + 512, lane);           // G2c1 -> B0
    CP_WAIT(1); a1 += dotR(fb[2], hr, lane);  stage16(bb[1], whs[3] + 512, lane);           // G3c1 -> B1
    CP_WAIT(1); a2 += dotR(fb[0], hr, lane);
    CP_WAIT(0); a3 += dotR(fb[1], hr, lane);

    // speculative pre-stage of step-1's first 3 chunks (ladder entry condition)
    stage16(bb[0], whs[0], lane);   // G0c0 -> B0
    stage16(bb[1], whs[1], lane);   // G1c0 -> B1
    stage16(bb[2], whs[2], lane);   // G2c0 -> B2

    a0 = warp_sum(a0); a1 = warp_sum(a1); a2 = warp_sum(a2); a3 = warp_sum(a3);
    if (lane == 0) {
        if (half == 0) {
            a0 += b_sum[0] + wfl[0]; a1 += b_sum[1] + wfl[1];
            a2 += b_sum[2] + wfl[2]; a3 += b_sum[3] + wfl[3];
        }
        s_acc[u][half][0] = a0; s_acc[u][half][1] = a1;
        s_acc[u][half][2] = a2; s_acc[u][half][3] = a3;
    }
    __syncthreads();
    if (half == 0) {
        const float av  = (lane < 4) ? (s_acc[u][0][lane] + s_acc[u][1][lane]) : 0.0f;
        const float act = (lane == 2) ? tanhf(av) : sigm(av);
        const float iv = __shfl_sync(0xffffffffu, act, 0);
        const float fv = __shfl_sync(0xffffffffu, act, 1);
        const float gv = __shfl_sync(0xffffffffu, act, 2);
        const float ov = __shfl_sync(0xffffffffu, act, 3);
        if (lane == 0) {
            const float cn = fv * cprev + iv * gv;
            const float hn = ov * tanhf(cn);
            cprev = cn;
            g_H[0][j] = hn; g_C[0][j] = cn;
            s_part[u] = hn * whj;
        }
    }
    __syncthreads();
    if (tid == 0) {
        float s = 0.0f;
        #pragma unroll
        for (int w = 0; w < UPB; w++) s += s_part[w];
        g_partial[0][blockIdx.x] = s;
    }
    grid_sync(gen_target);                 // h[0] + halt partials globally visible

    if (warp == 0) {
        const float4 v = ldcg4((const float4*)g_partial[0] + lane);
        const float  s = warp_sum(v.x + v.y + v.z + v.w);
        if (lane == 0) {
            const float p = sigm(s + bh);
            s_p[0] = p; csum += p;
            s_bcast[3] = (csum >= 1.0f - EPSH) ? 1.0f : 0.0f;
        }
    }
    __syncthreads();

    // ======== steps 1.. with exact early exit — same canonical ladder ========
    int t = 0;
    if (s_bcast[3] == 0.0f) {
        for (t = 1; t < NSTEPS; t++) {
            if (t > 1) {                       // t==1's first 3 chunks were pre-staged
                stage16(bb[0], whs[0], lane);   // G0c0 -> B0
                stage16(bb[1], whs[1], lane);   // G1c0 -> B1
                stage16(bb[2], whs[2], lane);   // G2c0 -> B2
            }
            hp4 = (const float4*)g_H[t - 1];
            #pragma unroll
            for (int k = 0; k < 4; k++) hr[k] = ldcg4(hp4 + half*256 + k*32 + lane);        // c0

            CP_WAIT(2); a0 = accih[0] + dotR(fb[0], hr, lane);
            CP_WAIT(1); a1 = accih[1] + dotR(fb[1], hr, lane);  stage16(bb[0], whs[3],       lane); // G3c0 -> B0
            CP_WAIT(1); a2 = accih[2] + dotR(fb[2], hr, lane);  stage16(bb[1], whs[0] + 512, lane); // G0c1 -> B1
            CP_WAIT(1); a3 = accih[3] + dotR(fb[0], hr, lane);  stage16(bb[2], whs[1] + 512, lane); // G1c1 -> B2
            #pragma unroll
            for (int k = 0; k < 4; k++) hr[k] = ldcg4(hp4 + half*256 + 128 + k*32 + lane);  // c1
            CP_WAIT(1); a0 += dotR(fb[1], hr, lane);  stage16(bb[0], whs[2] + 512, lane);           // G2c1 -> B0
            CP_WAIT(1); a1 += dotR(fb[2], hr, lane);  stage16(bb[1], whs[3] + 512, lane);           // G3c1 -> B1
            CP_WAIT(1); a2 += dotR(fb[0], hr, lane);
            CP_WAIT(0); a3 += dotR(fb[1], hr, lane);

            a0 = warp_sum(a0); a1 = warp_sum(a1); a2 = warp_sum(a2); a3 = warp_sum(a3);
            if (lane == 0) {
                if (half == 0) { a0 += b_sum[0]; a1 += b_sum[1]; a2 += b_sum[2]; a3 += b_sum[3]; }
                s_acc[u][half][0] = a0; s_acc[u][half][1] = a1;
                s_acc[u][half][2] = a2; s_acc[u][half][3] = a3;
            }
            __syncthreads();
            if (half == 0) {
                const float av  = (lane < 4) ? (s_acc[u][0][lane] + s_acc[u][1][lane]) : 0.0f;
                const float act = (lane == 2) ? tanhf(av) : sigm(av);
                const float iv = __shfl_sync(0xffffffffu, act, 0);
                const float fv = __shfl_sync(0xffffffffu, act, 1);
                const float gv = __shfl_sync(0xffffffffu, act, 2);
                const float ov = __shfl_sync(0xffffffffu, act, 3);
                if (lane == 0) {
                    const float cn = fv * cprev + iv * gv;
                    const float hn = ov * tanhf(cn);
                    cprev = cn;
                    g_H[t][j] = hn; g_C[t][j] = cn;
                    s_part[u] = hn * whj;
                }
            }
            __syncthreads();
            if (tid == 0) {
                float s = 0.0f;
                #pragma unroll
                for (int w = 0; w < UPB; w++) s += s_part[w];
                g_partial[t][blockIdx.x] = s;
            }
            grid_sync(gen_target);

            if (warp == 0) {
                const float4 v = ldcg4((const float4*)g_partial[t] + lane);
                const float  s = warp_sum(v.x + v.y + v.z + v.w);
                if (lane == 0) {
                    const float p = sigm(s + bh);
                    s_p[t] = p; csum += p;
                    s_bcast[3] = (csum >= 1.0f - EPSH) ? 1.0f : 0.0f;
                }
            }
            __syncthreads();
            if (s_bcast[3] != 0.0f) break;   // exact early exit: later steps weight 0
        }
    }
    // (If halt at t==0, 3 speculative groups stay outstanding; they only write
    //  per-warp buffers never read again. Harmless.)

    // ======== halting weights ========
    if (tid == 0) {
        const int   n  = (t < NSTEPS) ? t : MSTEPS;
        const float pn = s_p[n];
        const float r  = 1.0f - ((n > 0) ? (csum - pn) : 0.0f);
        float sumw = r;
        for (int i = 0; i < n; i++) sumw += s_p[i];
        s_bcast[0] = r; s_bcast[1] = sumw; s_bcast[2] = (float)n;
        if (blockIdx.x == 0)
            out[OUTSZ + 2 * HID] = (float)n + 1.0f + r;    // ponder
    }
    __syncthreads();
    const float r    = s_bcast[0];
    const float sumw = s_bcast[1];
    const int   n    = (int)s_bcast[2];

    // ---- h_out / c_out for this block's own units (from g_H/g_C, already visible) ----
    if (half == 0) {
        float hw = 0.0f, cw = 0.0f;
        for (int tt = lane; tt <= n; tt += 32) {
            const float wt = (tt < n) ? s_p[tt] : r;
            hw += wt * g_H[tt][j];
            cw += wt * g_C[tt][j];
        }
        hw = warp_sum(hw); cw = warp_sum(cw);
        if (lane == 0) {
            out[OUTSZ + j]       = hw;   // h_out
            out[OUTSZ + HID + j] = cw;   // c_out
        }
    }

    // ---- block-local full weighted-h vector into s_h (no grid barrier needed:
    //      every g_H[tt], tt<=n, was published by the loop's grid_sync at step tt) ----
    for (int col = tid; col < HID; col += NTHR) {
        float acc = 0.0f;
        for (int tt = 0; tt <= n; tt++) {
            const float wt = (tt < n) ? s_p[tt] : r;
            acc += wt * __ldcg(&g_H[tt][col]);
        }
        s_h[col] = acc;
    }
    __syncthreads();

    // ---- output = W_out @ hw + sum_w * b_out (4 warps per row; W_out L2-hot, hw in smem) ----
    {
        const int row = blockIdx.x * 8 + (warp >> 2);   // 0..1023
        const int q   = warp & 3;                        // 512-col quarter
        const float4* wr = (const float4*)(W_out + (size_t)row * HID) + q * 128;
        const float4* hv = (const float4*)s_h + q * 128;
        float acc = 0.0f;
        #pragma unroll
        for (int k = 0; k < 4; k++) {
            const int idx = k*32 + lane;
            const float4 v  = wr[idx];
            const float4 hh = hv[idx];
            acc += v.x*hh.x + v.y*hh.y + v.z*hh.z + v.w*hh.w;
        }
        acc = warp_sum(acc);
        if (lane == 0) s_wo[warp >> 2][q] = acc;
    }
    __syncthreads();
    if (tid < 8) {
        const int row = blockIdx.x * 8 + tid;
        out[row] = s_wo[tid][0] + s_wo[tid][1] + s_wo[tid][2] + s_wo[tid][3]
                 + sumw * b_out[row];
    }
}

extern "C" void kernel_launch(void* const* d_in, const int* in_sizes, int n_in,
                              void* d_out, int out_size) {
    const float* x      = (const float*)d_in[0];
    const float* h0     = (const float*)d_in[1];
    const float* c0     = (const float*)d_in[2];
    const float* W_ih   = (const float*)d_in[3];
    const float* b_ih   = (const float*)d_in[4];
    const float* W_hh   = (const float*)d_in[5];
    const float* b_hh   = (const float*)d_in[6];
    const float* w_halt = (const float*)d_in[7];
    const float* b_halt = (const float*)d_in[8];
    const float* W_out  = (const float*)d_in[9];
    const float* b_out  = (const float*)d_in[10];
    float* out = (float*)d_out;

    const int smem_bytes = (2048 + NWARP * 1536) * 4;   // 204800 B
    cudaFuncSetAttribute(act_lstm, cudaFuncAttributeMaxDynamicSharedMemorySize, smem_bytes);
    act_lstm<<<NBLK, NTHR, smem_bytes>>>(x, h0, c0, W_ih, b_ih, W_hh, b_hh,
                                         w_halt, b_halt, W_out, b_out, out);
}

// round 17
// speedup vs baseline: 1.1087x; 1.1087x over previous
#include <cuda_runtime.h>
#include <math.h>
#include <stdint.h>

#define INSZ   1024
#define HID    2048
#define OUTSZ  1024
#define MSTEPS 100
#define NSTEPS 101
#define EPSH   0.01f

#define NBLK   128
#define NTHR   1024
#define NWARP  32
#define UPB    16            // hidden units per block (2 warps per unit)

// ---- persistent scratch (device globals; no allocations allowed) ----
__device__ float g_H[NSTEPS][HID];
__device__ float g_C[NSTEPS][HID];
__device__ float g_partial[NSTEPS][NBLK];   // per-block halt-dot partials (overwritten, no init)
__device__ unsigned int g_count = 0;
__device__ unsigned int g_gen   = 0;

// Generation-counter grid barrier (persists across graph replays). PROVEN (R7..R12).
__device__ __forceinline__ void grid_sync(unsigned int &target) {
    __syncthreads();
    if (threadIdx.x == 0) {
        __threadfence();
        unsigned int a = atomicAdd(&g_count, 1u);
        if (a == NBLK - 1) {
            g_count = 0u;
            __threadfence();
            atomicAdd(&g_gen, 1u);
        } else {
            while (atomicAdd(&g_gen, 0u) < target) __nanosleep(40);
        }
        __threadfence();
        target++;
    }
    __syncthreads();
}

__device__ __forceinline__ float warp_sum(float v) {
    #pragma unroll
    for (int o = 16; o > 0; o >>= 1) v += __shfl_xor_sync(0xffffffffu, v, o);
    return v;
}

__device__ __forceinline__ float sigm(float v) { return 1.0f / (1.0f + expf(-v)); }

// ---- cp.async staging of one 512-float chunk into a 2KB buffer ----
__device__ __forceinline__ void stage16(uint32_t sbuf, const float* g, int lane) {
    #pragma unroll
    for (int o = 0; o < 4; o++)
        asm volatile("cp.async.cg.shared.global [%0], [%1], 16;"
                     :: "r"(sbuf + (uint32_t)((o*32 + lane)*16)),
                        "l"(g + (o*32 + lane)*4) : "memory");
    asm volatile("cp.async.commit_group;" ::: "memory");
}
// 4-byte variant for the unaligned (stride-1025) W_ih rows.
// W_ih is single-use: mark it L2::evict_first so it cannot displace the
// 64MB W_hh working set that step 1 re-reads from L2.
__device__ __forceinline__ void stage4(uint32_t sbuf, const float* g, int lane) {
    uint64_t pol;
    asm volatile("createpolicy.fractional.L2::evict_first.b64 %0, 1.0;" : "=l"(pol));
    #pragma unroll
    for (int o = 0; o < 16; o++)
        asm volatile("cp.async.ca.shared.global.L2::cache_hint [%0], [%1], 4, %2;"
                     :: "r"(sbuf + (uint32_t)((o*32 + lane)*4)),
                        "l"(g + (o*32 + lane)), "l"(pol) : "memory");
    asm volatile("cp.async.commit_group;" ::: "memory");
}
#define CP_WAIT(N) asm volatile("cp.async.wait_group %0;" :: "n"(N) : "memory")

// 512-float chunk dot: weights from smem, operand from registers
__device__ __forceinline__ float dotR(const float4* w, const float4 h[4], int lane) {
    float acc = 0.0f;
    #pragma unroll
    for (int k = 0; k < 4; k++) {
        const float4 wv = w[k*32 + lane];
        acc += wv.x*h[k].x + wv.y*h[k].y + wv.z*h[k].z + wv.w*h[k].w;
    }
    return acc;
}

__global__ __launch_bounds__(NTHR, 1) void act_lstm(
    const float* __restrict__ x,      const float* __restrict__ h0,
    const float* __restrict__ c0,     const float* __restrict__ W_ih,
    const float* __restrict__ b_ih,   const float* __restrict__ W_hh,
    const float* __restrict__ b_hh,   const float* __restrict__ w_halt,
    const float* __restrict__ b_halt, const float* __restrict__ W_out,
    const float* __restrict__ b_out,  float* __restrict__ out)
{
    const int tid  = threadIdx.x;
    const int warp = tid >> 5;
    const int lane = tid & 31;
    const int u    = warp >> 1;          // unit slot within block (0..15)
    const int half = warp & 1;           // K-half owned by this warp
    const int j    = blockIdx.x * UPB + u;

    extern __shared__ float dsm[];
    float* s_h = dsm;                    // 2048 floats
    float* s_x = dsm + 2048;             // 1024 floats
    float* wb  = dsm + 3072 + warp*1536; // per-warp 3 x 512-float buffers
    const float4* fb[3] = { (const float4*)wb, (const float4*)(wb + 512), (const float4*)(wb + 1024) };
    uint32_t bb0 = (uint32_t)__cvta_generic_to_shared(wb);
    uint32_t bb[3] = { bb0, bb0 + 2048u, bb0 + 4096u };
    const float4* sh4 = (const float4*)s_h;
    const float4* sx4 = (const float4*)s_x;

    __shared__ float s_acc[UPB][2][4];
    __shared__ float s_p[NSTEPS];
    __shared__ float s_part[UPB];
    __shared__ float s_bcast[4];         // [0]=r [1]=sum_w [2]=n [3]=halt flag
    __shared__ float s_wo[8][4];

    unsigned int gen_target = 0;
    if (tid == 0) gen_target = g_gen + 1u;

    // warp's 4 gate rows; each warp owns 1024 K-columns (2 chunks of 512)
    const float* ihs[4];
    const float* whs[4];
    #pragma unroll
    for (int g = 0; g < 4; g++) {
        const int row = j + g * HID;
        ihs[g] = W_ih + (size_t)row * (INSZ + 1) + 1 + half * (INSZ / 2);
        whs[g] = W_hh + (size_t)row * HID        +     half * (HID / 2);
    }

    // scalars on lane0/half0
    float b_sum[4] = {0,0,0,0}, wfl[4] = {0,0,0,0};
    float whj = 0.0f, cprev = 0.0f, bh = 0.0f, csum = 0.0f;
    if (half == 0 && lane == 0) {
        #pragma unroll
        for (int g = 0; g < 4; g++) {
            const int row = j + g * HID;
            b_sum[g] = b_ih[row] + b_hh[row];
            wfl[g]   = W_ih[(size_t)row * (INSZ + 1)];
        }
        whj   = w_halt[j];
        cprev = c0[j];
    }
    if (tid == 0) bh = b_halt[0];

    // ======== step 0: fused W_ih@x + W_hh@h0 — 12-chunk pipeline, 3-buffer rotation ========
    // chunk order (gate-major per operand): X0..X3, G0c0..G3c0, G0c1..G3c1
    stage4(bb[0], ihs[0], lane);                         // X0 -> B0
    stage4(bb[1], ihs[1], lane);                         // X1 -> B1
    stage4(bb[2], ihs[2], lane);                         // X2 -> B2

    // L2-prefetch this block's W_out rows for the epilogue (fire and forget)
    if (tid < 512) {
        const float* wop = W_out + (size_t)(blockIdx.x * 8) * HID + tid * 32;
        asm volatile("prefetch.global.L2 [%0];" :: "l"(wop));
    }

    s_x[tid]        = x[tid];
    s_h[tid]        = h0[tid];
    s_h[tid + 1024] = h0[tid + 1024];
    __syncthreads();

    // operand registers: xr / hr share storage
    float4 hr[4];
    #pragma unroll
    for (int k = 0; k < 4; k++) hr[k] = sx4[half*128 + k*32 + lane];   // x operand

    float accih[4];
    float a0, a1, a2, a3;
    CP_WAIT(2); accih[0] = dotR(fb[0], hr, lane);
    CP_WAIT(1); accih[1] = dotR(fb[1], hr, lane);  stage4 (bb[0], ihs[3],        lane);  // X3   -> B0
    CP_WAIT(1); accih[2] = dotR(fb[2], hr, lane);  stage16(bb[1], whs[0],        lane);  // G0c0 -> B1
    CP_WAIT(1); accih[3] = dotR(fb[0], hr, lane);  stage16(bb[2], whs[1],        lane);  // G1c0 -> B2
    #pragma unroll
    for (int k = 0; k < 4; k++) hr[k] = sh4[half*256 + k*32 + lane];   // h operand c0
    CP_WAIT(1); a0 = accih[0] + dotR(fb[1], hr, lane);  stage16(bb[0], whs[2],       lane);  // G2c0 -> B0
    CP_WAIT(1); a1 = accih[1] + dotR(fb[2], hr, lane);  stage16(bb[1], whs[3],       lane);  // G3c0 -> B1
    CP_WAIT(1); a2 = accih[2] + dotR(fb[0], hr, lane);  stage16(bb[2], whs[0] + 512, lane);  // G0c1 -> B2
    CP_WAIT(1); a3 = accih[3] + dotR(fb[1], hr, lane);  stage16(bb[0], whs[1] + 512, lane);  // G1c1 -> B0
    #pragma unroll
    for (int k = 0; k < 4; k++) hr[k] = sh4[half*256 + 128 + k*32 + lane];   // h operand c1
    CP_WAIT(1); a0 += dotR(fb[2], hr, lane);  stage16(bb[1], whs[2] + 512, lane);  // G2c1 -> B1
    CP_WAIT(1); a1 += dotR(fb[0], hr, lane);  stage16(bb[2], whs[3] + 512, lane);  // G3c1 -> B2
    CP_WAIT(1); a2 += dotR(fb[1], hr, lane);
    CP_WAIT(0); a3 += dotR(fb[2], hr, lane);

    // --- speculative pre-stage of step-1's first 3 chunks (loop expects
    //     L0=G0c0 in B0, L1=G1c0 in B1, L2=G2c0 in B2) ---
    stage16(bb[0], whs[0], lane);
    stage16(bb[1], whs[1], lane);
    stage16(bb[2], whs[2], lane);

    a0 = warp_sum(a0); a1 = warp_sum(a1); a2 = warp_sum(a2); a3 = warp_sum(a3);
    if (lane == 0) {
        if (half == 0) {
            a0 += b_sum[0] + wfl[0]; a1 += b_sum[1] + wfl[1];
            a2 += b_sum[2] + wfl[2]; a3 += b_sum[3] + wfl[3];
        }
        s_acc[u][half][0] = a0; s_acc[u][half][1] = a1;
        s_acc[u][half][2] = a2; s_acc[u][half][3] = a3;
    }
    __syncthreads();
    if (half == 0) {
        const float av  = (lane < 4) ? (s_acc[u][0][lane] + s_acc[u][1][lane]) : 0.0f;
        const float act = (lane == 2) ? tanhf(av) : sigm(av);
        const float iv = __shfl_sync(0xffffffffu, act, 0);
        const float fv = __shfl_sync(0xffffffffu, act, 1);
        const float gv = __shfl_sync(0xffffffffu, act, 2);
        const float ov = __shfl_sync(0xffffffffu, act, 3);
        if (lane == 0) {
            const float cn = fv * cprev + iv * gv;
            const float hn = ov * tanhf(cn);
            cprev = cn;
            g_H[0][j] = hn; g_C[0][j] = cn;
            s_part[u] = hn * whj;
        }
    }
    __syncthreads();
    if (tid == 0) {
        float s = 0.0f;
        #pragma unroll
        for (int w = 0; w < UPB; w++) s += s_part[w];
        g_partial[0][blockIdx.x] = s;
    }
    grid_sync(gen_target);                 // h[0] + halt partials globally visible

    if (warp == 0) {
        const float4 v = __ldcg((const float4*)g_partial[0] + lane);
        const float  s = warp_sum(v.x + v.y + v.z + v.w);
        if (lane == 0) {
            const float p = sigm(s + bh);
            s_p[0] = p; csum += p;
            s_bcast[3] = (csum >= 1.0f - EPSH) ? 1.0f : 0.0f;
        }
    }
    __syncthreads();

    // ======== steps 1.. with exact early exit — 8-chunk gate-major pipeline ========
    int t = 0;
    if (s_bcast[3] == 0.0f) {
        for (t = 1; t < NSTEPS; t++) {
            if (t > 1) {                       // t==1's first 3 chunks were pre-staged
                stage16(bb[0], whs[0], lane);   // G0c0 -> B0
                stage16(bb[1], whs[1], lane);   // G1c0 -> B1
                stage16(bb[2], whs[2], lane);   // G2c0 -> B2
            }
            const float* hp = g_H[t - 1];
            s_h[tid]        = __ldcg(hp + tid);
            s_h[tid + 1024] = __ldcg(hp + tid + 1024);
            __syncthreads();
            #pragma unroll
            for (int k = 0; k < 4; k++) hr[k] = sh4[half*256 + k*32 + lane];   // c0

            CP_WAIT(2); a0 = accih[0] + dotR(fb[0], hr, lane);
            CP_WAIT(1); a1 = accih[1] + dotR(fb[1], hr, lane);  stage16(bb[0], whs[3],       lane); // G3c0 -> B0
            CP_WAIT(1); a2 = accih[2] + dotR(fb[2], hr, lane);  stage16(bb[1], whs[0] + 512, lane); // G0c1 -> B1
            CP_WAIT(1); a3 = accih[3] + dotR(fb[0], hr, lane);  stage16(bb[2], whs[1] + 512, lane); // G1c1 -> B2
            #pragma unroll
            for (int k = 0; k < 4; k++) hr[k] = sh4[half*256 + 128 + k*32 + lane];   // c1
            CP_WAIT(1); a0 += dotR(fb[1], hr, lane);  stage16(bb[0], whs[2] + 512, lane); // G2c1 -> B0
            CP_WAIT(1); a1 += dotR(fb[2], hr, lane);  stage16(bb[1], whs[3] + 512, lane); // G3c1 -> B1
            CP_WAIT(1); a2 += dotR(fb[0], hr, lane);
            CP_WAIT(0); a3 += dotR(fb[1], hr, lane);

            a0 = warp_sum(a0); a1 = warp_sum(a1); a2 = warp_sum(a2); a3 = warp_sum(a3);
            if (lane == 0) {
                if (half == 0) { a0 += b_sum[0]; a1 += b_sum[1]; a2 += b_sum[2]; a3 += b_sum[3]; }
                s_acc[u][half][0] = a0; s_acc[u][half][1] = a1;
                s_acc[u][half][2] = a2; s_acc[u][half][3] = a3;
            }
            __syncthreads();
            if (half == 0) {
                const float av  = (lane < 4) ? (s_acc[u][0][lane] + s_acc[u][1][lane]) : 0.0f;
                const float act = (lane == 2) ? tanhf(av) : sigm(av);
                const float iv = __shfl_sync(0xffffffffu, act, 0);
                const float fv = __shfl_sync(0xffffffffu, act, 1);
                const float gv = __shfl_sync(0xffffffffu, act, 2);
                const float ov = __shfl_sync(0xffffffffu, act, 3);
                if (lane == 0) {
                    const float cn = fv * cprev + iv * gv;
                    const float hn = ov * tanhf(cn);
                    cprev = cn;
                    g_H[t][j] = hn; g_C[t][j] = cn;
                    s_part[u] = hn * whj;
                }
            }
            __syncthreads();
            if (tid == 0) {
                float s = 0.0f;
                #pragma unroll
                for (int w = 0; w < UPB; w++) s += s_part[w];
                g_partial[t][blockIdx.x] = s;
            }
            grid_sync(gen_target);

            if (warp == 0) {
                const float4 v = __ldcg((const float4*)g_partial[t] + lane);
                const float  s = warp_sum(v.x + v.y + v.z + v.w);
                if (lane == 0) {
                    const float p = sigm(s + bh);
                    s_p[t] = p; csum += p;
                    s_bcast[3] = (csum >= 1.0f - EPSH) ? 1.0f : 0.0f;
                }
            }
            __syncthreads();
            if (s_bcast[3] != 0.0f) break;   // exact early exit: later steps weight 0
        }
    }
    // (If halt at t==0, 3 speculative groups stay outstanding; they only write
    //  per-warp buffers never read again. Harmless.)

    // ======== halting weights ========
    if (tid == 0) {
        const int   n  = (t < NSTEPS) ? t : MSTEPS;
        const float pn = s_p[n];
        const float r  = 1.0f - ((n > 0) ? (csum - pn) : 0.0f);
        float sumw = r;
        for (int i = 0; i < n; i++) sumw += s_p[i];
        s_bcast[0] = r; s_bcast[1] = sumw; s_bcast[2] = (float)n;
        if (blockIdx.x == 0)
            out[OUTSZ + 2 * HID] = (float)n + 1.0f + r;    // ponder
    }
    __syncthreads();
    const float r    = s_bcast[0];
    const float sumw = s_bcast[1];
    const int   n    = (int)s_bcast[2];

    // ---- h_out / c_out for this block's own units (from g_H/g_C, already visible) ----
    if (half == 0) {
        float hw = 0.0f, cw = 0.0f;
        for (int tt = lane; tt <= n; tt += 32) {
            const float wt = (tt < n) ? s_p[tt] : r;
            hw += wt * g_H[tt][j];
            cw += wt * g_C[tt][j];
        }
        hw = warp_sum(hw); cw = warp_sum(cw);
        if (lane == 0) {
            out[OUTSZ + j]       = hw;   // h_out
            out[OUTSZ + HID + j] = cw;   // c_out
        }
    }

    // ---- block-local full weighted-h vector into s_h (no grid barrier needed:
    //      every g_H[tt], tt<=n, was published by the loop's grid_sync at step tt) ----
    for (int col = tid; col < HID; col += NTHR) {
        float acc = 0.0f;
        for (int tt = 0; tt <= n; tt++) {
            const float wt = (tt < n) ? s_p[tt] : r;
            acc += wt * __ldcg(&g_H[tt][col]);
        }
        s_h[col] = acc;
    }
    __syncthreads();

    // ---- output = W_out @ hw + sum_w * b_out (4 warps per row; W_out L2-hot, hw in smem) ----
    {
        const int row = blockIdx.x * 8 + (warp >> 2);   // 0..1023
        const int q   = warp & 3;                        // 512-col quarter
        const float4* wr = (const float4*)(W_out + (size_t)row * HID) + q * 128;
        const float4* hv = (const float4*)s_h + q * 128;
        float acc = 0.0f;
        #pragma unroll
        for (int k = 0; k < 4; k++) {
            const int idx = k*32 + lane;
            const float4 v  = wr[idx];
            const float4 hh = hv[idx];
            acc += v.x*hh.x + v.y*hh.y + v.z*hh.z + v.w*hh.w;
        }
        acc = warp_sum(acc);
        if (lane == 0) s_wo[warp >> 2][q] = acc;
    }
    __syncthreads();
    if (tid < 8) {
        const int row = blockIdx.x * 8 + tid;
        out[row] = s_wo[tid][0] + s_wo[tid][1] + s_wo[tid][2] + s_wo[tid][3]
                 + sumw * b_out[row];
    }
}

extern "C" void kernel_launch(void* const* d_in, const int* in_sizes, int n_in,
                              void* d_out, int out_size) {
    const float* x      = (const float*)d_in[0];
    const float* h0     = (const float*)d_in[1];
    const float* c0     = (const float*)d_in[2];
    const float* W_ih   = (const float*)d_in[3];
    const float* b_ih   = (const float*)d_in[4];
    const float* W_hh   = (const float*)d_in[5];
    const float* b_hh   = (const float*)d_in[6];
    const float* w_halt = (const float*)d_in[7];
    const float* b_halt = (const float*)d_in[8];
    const float* W_out  = (const float*)d_in[9];
    const float* b_out  = (const float*)d_in[10];
    float* out = (float*)d_out;

    const int smem_bytes = (3072 + NWARP * 1536) * 4;   // 208896 B
    cudaFuncSetAttribute(act_lstm, cudaFuncAttributeMaxDynamicSharedMemorySize, smem_bytes);
    act_lstm<<<NBLK, NTHR, smem_bytes>>>(x, h0, c0, W_ih, b_ih, W_hh, b_hh,
                                         w_halt, b_halt, W_out, b_out, out);
}